// round 1
// baseline (speedup 1.0000x reference)
#include <cuda_runtime.h>
#include <math.h>

#define NND 100000
#define NE  1600000
#define HID 128
#define OUTC 64
#define ENC_M 4

struct __align__(8) EdgeP { int src; float w; };

// ---- scratch (static device globals; no allocations) ----
__device__ float g_h [NND * HID];   // h / x0 per layer
__device__ float g_z0[NND * HID];   // ping
__device__ float g_z1[NND * HID];   // pong
__device__ EdgeP g_ep[NE];          // CSR payload {src, w}
__device__ int   g_rowptr[NND + 1];
__device__ int   g_cur[NND];        // counts, then cursors
__device__ int   g_bsum[128];
__device__ int   g_is64;

__device__ __forceinline__ float gelu_f(float v) {
    return 0.5f * v * (1.0f + erff(v * 0.70710678118654752f));
}

// ---------------- dtype detect (int64 vs int32 edge_index) ----------------
__global__ void detect_k(const int* __restrict__ ei32) {
    if (blockIdx.x == 0 && threadIdx.x == 0) {
        int ok = 1;
        #pragma unroll
        for (int j = 0; j < 16; j++) ok &= (ei32[2 * j + 1] == 0);
        g_is64 = ok;   // int64 little-endian: odd words are zero high-halves
    }
}

// ---------------- CSR build ----------------
__global__ void zero_cur_k() {
    int i = blockIdx.x * blockDim.x + threadIdx.x;
    if (i < NND) g_cur[i] = 0;
}

__global__ void hist_k(const void* __restrict__ ei) {
    int i = blockIdx.x * blockDim.x + threadIdx.x;
    if (i >= NE) return;
    int dst = g_is64 ? (int)((const long long*)ei)[NE + i]
                     : ((const int*)ei)[NE + i];
    atomicAdd(&g_cur[dst], 1);
}

__global__ void scan1_k() {          // block-wise exclusive scan, 1024 thr
    int tid = threadIdx.x, lane = tid & 31, wid = tid >> 5;
    int g = blockIdx.x * 1024 + tid;
    int v = (g < NND) ? g_cur[g] : 0;
    int x = v;
    #pragma unroll
    for (int d = 1; d < 32; d <<= 1) {
        int t = __shfl_up_sync(0xffffffffu, x, d);
        if (lane >= d) x += t;
    }
    __shared__ int ws[32];
    if (lane == 31) ws[wid] = x;
    __syncthreads();
    if (wid == 0) {
        int y = ws[lane];
        #pragma unroll
        for (int d = 1; d < 32; d <<= 1) {
            int t = __shfl_up_sync(0xffffffffu, y, d);
            if (lane >= d) y += t;
        }
        ws[lane] = y;
    }
    __syncthreads();
    int off = wid ? ws[wid - 1] : 0;
    int incl = x + off;
    if (g < NND) g_rowptr[g] = incl - v;        // exclusive within block
    if (tid == 1023) g_bsum[blockIdx.x] = incl; // block total
}

__global__ void scan2_k(int nb) {    // serial scan of 98 block sums
    if (threadIdx.x == 0 && blockIdx.x == 0) {
        int run = 0;
        for (int i = 0; i < nb; i++) { int t = g_bsum[i]; g_bsum[i] = run; run += t; }
        g_rowptr[NND] = run;
    }
}

__global__ void scan3_k() {
    int i = blockIdx.x * blockDim.x + threadIdx.x;
    if (i < NND) {
        int v = g_rowptr[i] + g_bsum[i >> 10];
        g_rowptr[i] = v;
        g_cur[i]    = v;   // cursor for fill
    }
}

__global__ void fill_k(const void* __restrict__ ei, const float* __restrict__ ew) {
    int i = blockIdx.x * blockDim.x + threadIdx.x;
    if (i >= NE) return;
    int src, dst;
    if (g_is64) {
        src = (int)((const long long*)ei)[i];
        dst = (int)((const long long*)ei)[NE + i];
    } else {
        src = ((const int*)ei)[i];
        dst = ((const int*)ei)[NE + i];
    }
    int pos = atomicAdd(&g_cur[dst], 1);
    EdgeP p; p.src = src; p.w = ew[i];
    g_ep[pos] = p;
}

// ---------------- encoder: h = gelu(LN(x @ Wenc^T)) ----------------
// blockDim=128. sW layout [c][k] padded stride 132 -> conflict-free float4 LDS.
__global__ void __launch_bounds__(128) encoder_k(
    const float* __restrict__ x, const float* __restrict__ W,
    const float* __restrict__ gamma, const float* __restrict__ beta)
{
    extern __shared__ __align__(16) float sm[];
    float* sW   = sm;                     // 128*132
    float* sx   = sW + 128 * 132;         // ENC_M*128
    float* ssum = sx + ENC_M * 128;       // ENC_M*4
    float* ssq  = ssum + ENC_M * 4;       // ENC_M*4

    const int tid = threadIdx.x, lane = tid & 31, wid = tid >> 5;
    for (int i = tid; i < HID * HID; i += 128) {
        int c = i >> 7, k = i & 127;
        sW[c * 132 + k] = W[i];
    }
    const float gm = gamma[tid], bt = beta[tid];
    __syncthreads();

    for (int base = blockIdx.x * ENC_M; base < NND; base += gridDim.x * ENC_M) {
        #pragma unroll
        for (int m = 0; m < ENC_M; m++) {
            int n = base + m;
            sx[m * 128 + tid] = (n < NND) ? x[n * 128 + tid] : 0.f;
        }
        __syncthreads();

        float acc[ENC_M] = {0.f, 0.f, 0.f, 0.f};
        #pragma unroll 4
        for (int k = 0; k < 128; k += 4) {
            float4 w4 = *(const float4*)(sW + tid * 132 + k);
            #pragma unroll
            for (int m = 0; m < ENC_M; m++) {
                float4 xv = *(const float4*)(sx + m * 128 + k);
                acc[m] += w4.x * xv.x + w4.y * xv.y + w4.z * xv.z + w4.w * xv.w;
            }
        }

        #pragma unroll
        for (int m = 0; m < ENC_M; m++) {
            float s = acc[m], q = acc[m] * acc[m];
            #pragma unroll
            for (int o = 16; o; o >>= 1) {
                s += __shfl_xor_sync(0xffffffffu, s, o);
                q += __shfl_xor_sync(0xffffffffu, q, o);
            }
            if (lane == 0) { ssum[m * 4 + wid] = s; ssq[m * 4 + wid] = q; }
        }
        __syncthreads();
        #pragma unroll
        for (int m = 0; m < ENC_M; m++) {
            float S = ssum[m * 4] + ssum[m * 4 + 1] + ssum[m * 4 + 2] + ssum[m * 4 + 3];
            float Q = ssq [m * 4] + ssq [m * 4 + 1] + ssq [m * 4 + 2] + ssq [m * 4 + 3];
            float mu  = S * (1.f / 128.f);
            float var = Q * (1.f / 128.f) - mu * mu;
            float inv = rsqrtf(var + 1e-5f);
            float v = gm * (acc[m] - mu) * inv + bt;
            v = gelu_f(v);
            int n = base + m;
            if (n < NND) g_h[n * 128 + tid] = v;
        }
        __syncthreads();
    }
}

// ---------------- propagation step (warp per node) ----------------
// out[n] = 0.9 * sum_e w_e * z[src_e] + 0.1 * x0[n]; fuse=1 -> gelu + LN epilogue
__global__ void __launch_bounds__(256) prop_k(
    const float4* __restrict__ z4, const float4* x04, float4* o4,
    const float4* __restrict__ gamma4, const float4* __restrict__ beta4, int fuse)
{
    int w = (blockIdx.x * blockDim.x + threadIdx.x) >> 5;
    int lane = threadIdx.x & 31;
    if (w >= NND) return;
    int beg = g_rowptr[w], end = g_rowptr[w + 1];

    float4 acc = make_float4(0.f, 0.f, 0.f, 0.f);
    int e = beg;
    for (; e + 4 <= end; e += 4) {
        EdgeP p0 = g_ep[e], p1 = g_ep[e + 1], p2 = g_ep[e + 2], p3 = g_ep[e + 3];
        float4 a = z4[p0.src * 32 + lane];
        float4 b = z4[p1.src * 32 + lane];
        float4 c = z4[p2.src * 32 + lane];
        float4 d = z4[p3.src * 32 + lane];
        acc.x += p0.w * a.x; acc.y += p0.w * a.y; acc.z += p0.w * a.z; acc.w += p0.w * a.w;
        acc.x += p1.w * b.x; acc.y += p1.w * b.y; acc.z += p1.w * b.z; acc.w += p1.w * b.w;
        acc.x += p2.w * c.x; acc.y += p2.w * c.y; acc.z += p2.w * c.z; acc.w += p2.w * c.w;
        acc.x += p3.w * d.x; acc.y += p3.w * d.y; acc.z += p3.w * d.z; acc.w += p3.w * d.w;
    }
    for (; e < end; e++) {
        EdgeP p = g_ep[e];
        float4 a = z4[p.src * 32 + lane];
        acc.x += p.w * a.x; acc.y += p.w * a.y; acc.z += p.w * a.z; acc.w += p.w * a.w;
    }

    float4 xv = x04[w * 32 + lane];
    float4 r;
    r.x = 0.9f * acc.x + 0.1f * xv.x;
    r.y = 0.9f * acc.y + 0.1f * xv.y;
    r.z = 0.9f * acc.z + 0.1f * xv.z;
    r.w = 0.9f * acc.w + 0.1f * xv.w;

    if (fuse) {
        r.x = gelu_f(r.x); r.y = gelu_f(r.y); r.z = gelu_f(r.z); r.w = gelu_f(r.w);
        float s = r.x + r.y + r.z + r.w;
        float q = r.x * r.x + r.y * r.y + r.z * r.z + r.w * r.w;
        #pragma unroll
        for (int o = 16; o; o >>= 1) {
            s += __shfl_xor_sync(0xffffffffu, s, o);
            q += __shfl_xor_sync(0xffffffffu, q, o);
        }
        float mu  = s * (1.f / 128.f);
        float var = q * (1.f / 128.f) - mu * mu;
        float inv = rsqrtf(var + 1e-5f);
        float4 gmv = gamma4[lane], btv = beta4[lane];
        r.x = gmv.x * (r.x - mu) * inv + btv.x;
        r.y = gmv.y * (r.y - mu) * inv + btv.y;
        r.z = gmv.z * (r.z - mu) * inv + btv.z;
        r.w = gmv.w * (r.w - mu) * inv + btv.w;
    }
    o4[w * 32 + lane] = r;
}

// ---------------- decoder: out = h @ Wdec^T ----------------
// blockDim=256 = 4 sub-blocks of 64 lanes; each sub computes one node row.
__global__ void __launch_bounds__(256) decoder_k(
    const float* __restrict__ Wd, float* __restrict__ out)
{
    __shared__ __align__(16) float sW[OUTC * 132];
    __shared__ __align__(16) float sx[4 * 128];
    const int tid = threadIdx.x;
    for (int i = tid; i < OUTC * HID; i += 256) {
        int c = i >> 7, k = i & 127;
        sW[c * 132 + k] = Wd[i];
    }
    __syncthreads();
    const int sub = tid >> 6, c = tid & 63;

    for (int base = blockIdx.x * 4; base < NND; base += gridDim.x * 4) {
        for (int i = tid; i < 4 * 128; i += 256) {
            int n = base + (i >> 7);
            sx[i] = (n < NND) ? g_h[n * 128 + (i & 127)] : 0.f;
        }
        __syncthreads();
        float acc = 0.f;
        #pragma unroll 4
        for (int k = 0; k < 128; k += 4) {
            float4 w4 = *(const float4*)(sW + c * 132 + k);
            float4 xv = *(const float4*)(sx + sub * 128 + k);
            acc += w4.x * xv.x + w4.y * xv.y + w4.z * xv.z + w4.w * xv.w;
        }
        int n = base + sub;
        if (n < NND) out[n * 64 + c] = acc;
        __syncthreads();
    }
}

// ---------------- launch ----------------
extern "C" void kernel_launch(void* const* d_in, const int* in_sizes, int n_in,
                              void* d_out, int out_size)
{
    const float* x     = (const float*)d_in[0];
    const void*  ei    = (const void*) d_in[1];
    const float* ew    = (const float*)d_in[2];
    const float* Wenc  = (const float*)d_in[3];
    const float* Wdec  = (const float*)d_in[4];
    const float* gamma = (const float*)d_in[5];
    const float* beta  = (const float*)d_in[6];
    float* out = (float*)d_out;

    void *ph, *pz0, *pz1;
    cudaGetSymbolAddress(&ph,  g_h);
    cudaGetSymbolAddress(&pz0, g_z0);
    cudaGetSymbolAddress(&pz1, g_z1);
    float4* h4  = (float4*)ph;
    float4* z04 = (float4*)pz0;
    float4* z14 = (float4*)pz1;

    const int NB_SCAN = (NND + 1023) / 1024;   // 98

    detect_k<<<1, 32>>>((const int*)ei);
    zero_cur_k<<<(NND + 255) / 256, 256>>>();
    hist_k<<<(NE + 255) / 256, 256>>>(ei);
    scan1_k<<<NB_SCAN, 1024>>>();
    scan2_k<<<1, 32>>>(NB_SCAN);
    scan3_k<<<(NND + 255) / 256, 256>>>();
    fill_k<<<(NE + 255) / 256, 256>>>(ei, ew);

    int enc_smem = (128 * 132 + ENC_M * 128 + ENC_M * 8) * (int)sizeof(float);
    cudaFuncSetAttribute(encoder_k, cudaFuncAttributeMaxDynamicSharedMemorySize, enc_smem);
    encoder_k<<<444, 128, enc_smem>>>(x, Wenc, gamma, beta);

    const float4* g4 = (const float4*)gamma;
    const float4* b4 = (const float4*)beta;
    const int pblocks = (NND * 32) / 256;      // 12500, exact

    for (int layer = 0; layer < 4; layer++) {
        // s=0: h -> z0
        prop_k<<<pblocks, 256>>>(h4, h4, z04, g4, b4, 0);
        // s=1..8: ping-pong (odd s: z0->z1, even s: z1->z0)
        for (int s = 1; s < 9; s++) {
            const float4* in = (s & 1) ? z04 : z14;
            float4*       o  = (s & 1) ? z14 : z04;
            prop_k<<<pblocks, 256>>>(in, h4, o, g4, b4, 0);
        }
        // s=9: z0 -> h with fused gelu+LN (safe: x0[n] read before h[n] write, per-node)
        prop_k<<<pblocks, 256>>>(z04, h4, h4, g4, b4, 1);
    }

    decoder_k<<<888, 256>>>(Wdec, out);
}

// round 4
// speedup vs baseline: 1.4037x; 1.4037x over previous
#include <cuda_runtime.h>
#include <cuda_fp16.h>
#include <math.h>

#define NND 100000
#define NE  1600000
#define HID 128
#define OUTC 64
#define ENC_M 4

struct __align__(8) EdgeP { int src; float w; };

// ---- scratch (static device globals; no allocations) ----
__device__ uint2 g_h16[NND * 32];   // h / x0 per layer (fp16, 4 halves per lane)
__device__ uint2 g_za [NND * 32];   // ping (fp16, scaled state s_k)
__device__ uint2 g_zb [NND * 32];   // pong
__device__ EdgeP g_ep[NE];          // CSR payload {src, w}
__device__ int   g_rowptr[NND + 1];
__device__ int   g_cur[NND];
__device__ int   g_bsum[128];
__device__ int   g_is64;

__device__ __forceinline__ float gelu_f(float v) {
    return 0.5f * v * (1.0f + erff(v * 0.70710678118654752f));
}

__device__ __forceinline__ float4 ld16(const uint2* __restrict__ z, int row, int lane) {
    uint2 u = z[row * 32 + lane];
    __half2 a = *(__half2*)&u.x;
    __half2 b = *(__half2*)&u.y;
    float2 fa = __half22float2(a), fb = __half22float2(b);
    return make_float4(fa.x, fa.y, fb.x, fb.y);
}

__device__ __forceinline__ void st16(uint2* __restrict__ z, int row, int lane, float4 v) {
    __half2 a = __floats2half2_rn(v.x, v.y);
    __half2 b = __floats2half2_rn(v.z, v.w);
    uint2 u;
    u.x = *(unsigned*)&a;
    u.y = *(unsigned*)&b;
    z[row * 32 + lane] = u;
}

// ---------------- dtype detect (int64 vs int32 edge_index) ----------------
__global__ void detect_k(const int* __restrict__ ei32) {
    if (blockIdx.x == 0 && threadIdx.x == 0) {
        int ok = 1;
        #pragma unroll
        for (int j = 0; j < 16; j++) ok &= (ei32[2 * j + 1] == 0);
        g_is64 = ok;
    }
}

// ---------------- CSR build ----------------
__global__ void zero_cur_k() {
    int i = blockIdx.x * blockDim.x + threadIdx.x;
    if (i < NND) g_cur[i] = 0;
}

__global__ void hist_k(const void* __restrict__ ei) {
    int i = blockIdx.x * blockDim.x + threadIdx.x;
    if (i >= NE) return;
    int dst = g_is64 ? (int)((const long long*)ei)[NE + i]
                     : ((const int*)ei)[NE + i];
    atomicAdd(&g_cur[dst], 1);
}

__global__ void scan1_k() {
    int tid = threadIdx.x, lane = tid & 31, wid = tid >> 5;
    int g = blockIdx.x * 1024 + tid;
    int v = (g < NND) ? g_cur[g] : 0;
    int x = v;
    #pragma unroll
    for (int d = 1; d < 32; d <<= 1) {
        int t = __shfl_up_sync(0xffffffffu, x, d);
        if (lane >= d) x += t;
    }
    __shared__ int ws[32];
    if (lane == 31) ws[wid] = x;
    __syncthreads();
    if (wid == 0) {
        int y = ws[lane];
        #pragma unroll
        for (int d = 1; d < 32; d <<= 1) {
            int t = __shfl_up_sync(0xffffffffu, y, d);
            if (lane >= d) y += t;
        }
        ws[lane] = y;
    }
    __syncthreads();
    int off = wid ? ws[wid - 1] : 0;
    int incl = x + off;
    if (g < NND) g_rowptr[g] = incl - v;
    if (tid == 1023) g_bsum[blockIdx.x] = incl;
}

__global__ void scan2_k(int nb) {
    if (threadIdx.x == 0 && blockIdx.x == 0) {
        int run = 0;
        for (int i = 0; i < nb; i++) { int t = g_bsum[i]; g_bsum[i] = run; run += t; }
        g_rowptr[NND] = run;
    }
}

__global__ void scan3_k() {
    int i = blockIdx.x * blockDim.x + threadIdx.x;
    if (i < NND) {
        int v = g_rowptr[i] + g_bsum[i >> 10];
        g_rowptr[i] = v;
        g_cur[i]    = v;
    }
}

__global__ void fill_k(const void* __restrict__ ei, const float* __restrict__ ew) {
    int i = blockIdx.x * blockDim.x + threadIdx.x;
    if (i >= NE) return;
    int src, dst;
    if (g_is64) {
        src = (int)((const long long*)ei)[i];
        dst = (int)((const long long*)ei)[NE + i];
    } else {
        src = ((const int*)ei)[i];
        dst = ((const int*)ei)[NE + i];
    }
    int pos = atomicAdd(&g_cur[dst], 1);
    EdgeP p; p.src = src; p.w = ew[i];
    g_ep[pos] = p;
}

// ---------------- encoder: h16 = fp16(gelu(LN(x @ Wenc^T))) ----------------
__global__ void __launch_bounds__(128) encoder_k(
    const float* __restrict__ x, const float* __restrict__ W,
    const float* __restrict__ gamma, const float* __restrict__ beta)
{
    extern __shared__ __align__(16) float sm[];
    float* sW   = sm;                     // 128*132
    float* sx   = sW + 128 * 132;         // ENC_M*128
    float* ssum = sx + ENC_M * 128;       // ENC_M*4
    float* ssq  = ssum + ENC_M * 4;       // ENC_M*4

    const int tid = threadIdx.x, lane = tid & 31, wid = tid >> 5;
    for (int i = tid; i < HID * HID; i += 128) {
        int c = i >> 7, k = i & 127;
        sW[c * 132 + k] = W[i];
    }
    const float gm = gamma[tid], bt = beta[tid];
    __half* h16 = (__half*)g_h16;
    __syncthreads();

    for (int base = blockIdx.x * ENC_M; base < NND; base += gridDim.x * ENC_M) {
        #pragma unroll
        for (int m = 0; m < ENC_M; m++) {
            int n = base + m;
            sx[m * 128 + tid] = (n < NND) ? x[n * 128 + tid] : 0.f;
        }
        __syncthreads();

        float acc[ENC_M] = {0.f, 0.f, 0.f, 0.f};
        #pragma unroll 4
        for (int k = 0; k < 128; k += 4) {
            float4 w4 = *(const float4*)(sW + tid * 132 + k);
            #pragma unroll
            for (int m = 0; m < ENC_M; m++) {
                float4 xv = *(const float4*)(sx + m * 128 + k);
                acc[m] += w4.x * xv.x + w4.y * xv.y + w4.z * xv.z + w4.w * xv.w;
            }
        }

        #pragma unroll
        for (int m = 0; m < ENC_M; m++) {
            float s = acc[m], q = acc[m] * acc[m];
            #pragma unroll
            for (int o = 16; o; o >>= 1) {
                s += __shfl_xor_sync(0xffffffffu, s, o);
                q += __shfl_xor_sync(0xffffffffu, q, o);
            }
            if (lane == 0) { ssum[m * 4 + wid] = s; ssq[m * 4 + wid] = q; }
        }
        __syncthreads();
        #pragma unroll
        for (int m = 0; m < ENC_M; m++) {
            float S = ssum[m * 4] + ssum[m * 4 + 1] + ssum[m * 4 + 2] + ssum[m * 4 + 3];
            float Q = ssq [m * 4] + ssq [m * 4 + 1] + ssq [m * 4 + 2] + ssq [m * 4 + 3];
            float mu  = S * (1.f / 128.f);
            float var = Q * (1.f / 128.f) - mu * mu;
            float inv = rsqrtf(var + 1e-5f);
            float v = gm * (acc[m] - mu) * inv + bt;
            v = gelu_f(v);
            int n = base + m;
            if (n < NND) h16[n * 128 + tid] = __float2half_rn(v);
        }
        __syncthreads();
    }
}

// ---------------- propagation step (warp per node, fp16 scaled state) ----------------
// Stored state s_k = z_k / 8^k.  s_{k+1} = cA * sum_e w_e * s_k[src] + cX * x0
// with cA = 0.9/8, cX = 0.1 * 8^-(k+1).
// fuse=1: z = s_10 * 8^10, then gelu + two-pass LN, write h16 for next layer.
__global__ void __launch_bounds__(256) prop16_k(
    const uint2* __restrict__ z, const uint2* __restrict__ x0, uint2* __restrict__ o,
    const float4* __restrict__ gamma4, const float4* __restrict__ beta4,
    float cA, float cX, int fuse)
{
    int w = (blockIdx.x * blockDim.x + threadIdx.x) >> 5;
    int lane = threadIdx.x & 31;
    if (w >= NND) return;
    int beg = g_rowptr[w], end = g_rowptr[w + 1];

    float4 acc = make_float4(0.f, 0.f, 0.f, 0.f);
    int e = beg;
    for (; e + 4 <= end; e += 4) {
        EdgeP p0 = g_ep[e], p1 = g_ep[e + 1], p2 = g_ep[e + 2], p3 = g_ep[e + 3];
        float4 a = ld16(z, p0.src, lane);
        float4 b = ld16(z, p1.src, lane);
        float4 c = ld16(z, p2.src, lane);
        float4 d = ld16(z, p3.src, lane);
        acc.x += p0.w * a.x; acc.y += p0.w * a.y; acc.z += p0.w * a.z; acc.w += p0.w * a.w;
        acc.x += p1.w * b.x; acc.y += p1.w * b.y; acc.z += p1.w * b.z; acc.w += p1.w * b.w;
        acc.x += p2.w * c.x; acc.y += p2.w * c.y; acc.z += p2.w * c.z; acc.w += p2.w * c.w;
        acc.x += p3.w * d.x; acc.y += p3.w * d.y; acc.z += p3.w * d.z; acc.w += p3.w * d.w;
    }
    for (; e < end; e++) {
        EdgeP p = g_ep[e];
        float4 a = ld16(z, p.src, lane);
        acc.x += p.w * a.x; acc.y += p.w * a.y; acc.z += p.w * a.z; acc.w += p.w * a.w;
    }

    float4 xv = ld16(x0, w, lane);
    float4 r;
    r.x = cA * acc.x + cX * xv.x;
    r.y = cA * acc.y + cX * xv.y;
    r.z = cA * acc.z + cX * xv.z;
    r.w = cA * acc.w + cX * xv.w;

    if (fuse) {
        const float FS = 1073741824.0f;   // 8^10 = 2^30, exact
        r.x = gelu_f(r.x * FS); r.y = gelu_f(r.y * FS);
        r.z = gelu_f(r.z * FS); r.w = gelu_f(r.w * FS);
        // two-pass LN (matches jax: mean first, then mean of squared deviation)
        float s = r.x + r.y + r.z + r.w;
        #pragma unroll
        for (int off = 16; off; off >>= 1)
            s += __shfl_xor_sync(0xffffffffu, s, off);
        float mu = s * (1.f / 128.f);
        float dx = r.x - mu, dy = r.y - mu, dz = r.z - mu, dw = r.w - mu;
        float q = dx * dx + dy * dy + dz * dz + dw * dw;
        #pragma unroll
        for (int off = 16; off; off >>= 1)
            q += __shfl_xor_sync(0xffffffffu, q, off);
        float var = q * (1.f / 128.f);
        float inv = rsqrtf(var + 1e-5f);
        float4 gmv = gamma4[lane], btv = beta4[lane];
        r.x = gmv.x * dx * inv + btv.x;
        r.y = gmv.y * dy * inv + btv.y;
        r.z = gmv.z * dz * inv + btv.z;
        r.w = gmv.w * dw * inv + btv.w;
    }
    st16(o, w, lane, r);
}

// ---------------- decoder: out = h16 @ Wdec^T ----------------
__global__ void __launch_bounds__(256) decoder_k(
    const float* __restrict__ Wd, float* __restrict__ out)
{
    __shared__ __align__(16) float sW[OUTC * 132];
    __shared__ __align__(16) float sx[4 * 128];
    const int tid = threadIdx.x;
    for (int i = tid; i < OUTC * HID; i += 256) {
        int c = i >> 7, k = i & 127;
        sW[c * 132 + k] = Wd[i];
    }
    __syncthreads();
    const int sub = tid >> 6, c = tid & 63;

    for (int base = blockIdx.x * 4; base < NND; base += gridDim.x * 4) {
        if (tid < 128) {
            int m = tid >> 5, l = tid & 31;
            int n = base + m;
            float4 v = (n < NND) ? ld16(g_h16, n, l)
                                 : make_float4(0.f, 0.f, 0.f, 0.f);
            *(float4*)(sx + m * 128 + l * 4) = v;
        }
        __syncthreads();
        float acc = 0.f;
        #pragma unroll 4
        for (int k = 0; k < 128; k += 4) {
            float4 w4 = *(const float4*)(sW + c * 132 + k);
            float4 xv = *(const float4*)(sx + sub * 128 + k);
            acc += w4.x * xv.x + w4.y * xv.y + w4.z * xv.z + w4.w * xv.w;
        }
        int n = base + sub;
        if (n < NND) out[n * 64 + c] = acc;
        __syncthreads();
    }
}

// ---------------- launch ----------------
extern "C" void kernel_launch(void* const* d_in, const int* in_sizes, int n_in,
                              void* d_out, int out_size)
{
    const float* x     = (const float*)d_in[0];
    const void*  ei    = (const void*) d_in[1];
    const float* ew    = (const float*)d_in[2];
    const float* Wenc  = (const float*)d_in[3];
    const float* Wdec  = (const float*)d_in[4];
    const float* gamma = (const float*)d_in[5];
    const float* beta  = (const float*)d_in[6];
    float* out = (float*)d_out;

    void *ph, *pza, *pzb;
    cudaGetSymbolAddress(&ph,  g_h16);
    cudaGetSymbolAddress(&pza, g_za);
    cudaGetSymbolAddress(&pzb, g_zb);
    uint2* h16 = (uint2*)ph;
    uint2* za  = (uint2*)pza;
    uint2* zb  = (uint2*)pzb;

    const int NB_SCAN = (NND + 1023) / 1024;   // 98

    detect_k<<<1, 32>>>((const int*)ei);
    zero_cur_k<<<(NND + 255) / 256, 256>>>();
    hist_k<<<(NE + 255) / 256, 256>>>(ei);
    scan1_k<<<NB_SCAN, 1024>>>();
    scan2_k<<<1, 32>>>(NB_SCAN);
    scan3_k<<<(NND + 255) / 256, 256>>>();
    fill_k<<<(NE + 255) / 256, 256>>>(ei, ew);

    int enc_smem = (128 * 132 + ENC_M * 128 + ENC_M * 8) * (int)sizeof(float);
    cudaFuncSetAttribute(encoder_k, cudaFuncAttributeMaxDynamicSharedMemorySize, enc_smem);
    encoder_k<<<444, 128, enc_smem>>>(x, Wenc, gamma, beta);

    const float4* g4 = (const float4*)gamma;
    const float4* b4 = (const float4*)beta;
    const int pblocks = (NND * 32) / 256;      // 12500

    const float cA = 0.9f / 8.0f;
    // cX[k] = 0.1 * 8^-(k+1), k = 0..9
    float cX[10];
    {
        float p = 1.0f;
        for (int k = 0; k < 10; k++) { p *= 0.125f; cX[k] = 0.1f * p; }
    }

    for (int layer = 0; layer < 4; layer++) {
        // k=0: h16 -> za
        prop16_k<<<pblocks, 256>>>(h16, h16, za, g4, b4, cA, cX[0], 0);
        // k=1..8: ping-pong (k odd: za->zb, k even: zb->za)
        for (int k = 1; k < 9; k++) {
            const uint2* in = (k & 1) ? za : zb;
            uint2*       o  = (k & 1) ? zb : za;
            prop16_k<<<pblocks, 256>>>(in, h16, o, g4, b4, cA, cX[k], 0);
        }
        // k=9: za -> h16 with unscale + gelu + two-pass LN
        prop16_k<<<pblocks, 256>>>(za, h16, h16, g4, b4, cA, cX[9], 1);
    }

    decoder_k<<<888, 256>>>(Wdec, out);
}